// round 3
// baseline (speedup 1.0000x reference)
#include <cuda_runtime.h>
#include <math.h>

// Problem constants (fixed by the dataset)
#define NN 50000      // nodes
#define F0 600        // input features
#define F1 628        // hidden features
#define F2 64         // output features
#define EE 400000     // edges

// ---------------- scratch (device globals: no allocations allowed) ----------
__device__ int   g_cnt   [NN];        // in-degree (excl. self-loop)
__device__ int   g_rowSt [NN];        // exclusive prefix of cnt
__device__ int   g_cursor[NN];        // fill cursors
__device__ int   g_bsum  [64];        // scan block sums
__device__ float g_dinv  [NN];
__device__ int   g_eSrc  [EE];        // CSR: src node per slot
__device__ float g_eW    [EE];        // CSR: dinv[s]*dinv[d] per slot
__device__ float g_H1[(size_t)NN * F1];   // x @ W1
__device__ float g_A1[(size_t)NN * F1];   // aggregated + bias + relu
__device__ float g_H2[(size_t)NN * F2];   // A1 @ W2
__device__ float g_Z [(size_t)NN * F2];   // aggregated + bias

// ---------------- degree / normalization / CSR build ------------------------
__global__ void k_zero_cnt(int* cnt, int n) {
    int i = blockIdx.x * blockDim.x + threadIdx.x;
    if (i < n) cnt[i] = 0;
}
__global__ void k_count(int* cnt, const int* __restrict__ dst, int e) {
    int i = blockIdx.x * blockDim.x + threadIdx.x;
    if (i < e) atomicAdd(&cnt[dst[i]], 1);
}
__global__ void k_dinv(float* dinv, const int* __restrict__ cnt, int n) {
    int i = blockIdx.x * blockDim.x + threadIdx.x;
    if (i < n) dinv[i] = rsqrtf((float)(cnt[i] + 1));   // +1 self-loop
}

#define SCAN_BLK 1024
__global__ void k_scan1(const int* __restrict__ cnt, int* __restrict__ excl,
                        int* __restrict__ bsum, int n)
{
    __shared__ int sh[SCAN_BLK];
    int i = blockIdx.x * SCAN_BLK + threadIdx.x;
    int v = (i < n) ? cnt[i] : 0;
    sh[threadIdx.x] = v;
    __syncthreads();
    #pragma unroll
    for (int off = 1; off < SCAN_BLK; off <<= 1) {
        int t = (threadIdx.x >= off) ? sh[threadIdx.x - off] : 0;
        __syncthreads();
        sh[threadIdx.x] += t;
        __syncthreads();
    }
    if (i < n) excl[i] = sh[threadIdx.x] - v;            // exclusive within block
    if (threadIdx.x == SCAN_BLK - 1) bsum[blockIdx.x] = sh[threadIdx.x];
}
__global__ void k_scan2(int* bsum, int nb) {
    if (threadIdx.x == 0 && blockIdx.x == 0) {
        int s = 0;
        for (int i = 0; i < nb; i++) { int t = bsum[i]; bsum[i] = s; s += t; }
    }
}
__global__ void k_scan3(int* __restrict__ excl, const int* __restrict__ bsum,
                        int* __restrict__ cursor, int n)
{
    int i = blockIdx.x * SCAN_BLK + threadIdx.x;
    if (i < n) {
        int r = excl[i] + bsum[blockIdx.x];
        excl[i] = r;
        cursor[i] = r;
    }
}
__global__ void k_fill(const int* __restrict__ src, const int* __restrict__ dst,
                       int* cursor, int* __restrict__ eSrc, float* __restrict__ eW,
                       const float* __restrict__ dinv, int e)
{
    int i = blockIdx.x * blockDim.x + threadIdx.x;
    if (i < e) {
        int s = src[i], d = dst[i];
        int pos = atomicAdd(&cursor[d], 1);
        eSrc[pos] = s;
        eW[pos]   = dinv[s] * dinv[d];
    }
}

// ---------------- tiled SGEMM: C[M,N] = A[M,K] @ B[K,N] ---------------------
// 256 threads, BM=128, BK=16, templated BN/TN. Double-buffered smem,
// float4 global loads (K,N always multiples of 4 here).
#define BM 128
#define BK 16

template <int BN_, int TN_>
__global__ __launch_bounds__(256) void k_sgemm(
    const float* __restrict__ A, const float* __restrict__ B,
    float* __restrict__ C, int M, int N, int K)
{
    static_assert(BN_ / TN_ == 16, "16 col groups required");
    constexpr int NV = BN_ / 64;            // float4s per thread for B tile

    __shared__ __align__(16) float As[2][BK][BM];
    __shared__ __align__(16) float Bs[2][BK][BN_ + 4];

    const int tid = threadIdx.x;
    const int tx  = tid & 15;               // col group (TN_ cols)
    const int ty  = tid >> 4;               // row group (8 rows)
    const int rowBase = blockIdx.y * BM;
    const int colBase = blockIdx.x * BN_;

    // A tile (128x16): 2 threads/row, 8 consecutive k each (2 float4)
    const int aRow = tid >> 1;
    const int aK   = (tid & 1) * 8;
    // B tile (16xBN_): 16 threads/row, 4*NV consecutive cols each
    const int bRow = tid >> 4;
    const int bCol = (tid & 15) * 4 * NV;

    float acc[8][TN_];
    #pragma unroll
    for (int i = 0; i < 8; i++)
        #pragma unroll
        for (int j = 0; j < TN_; j++) acc[i][j] = 0.0f;

    float4 aReg[2], bReg[NV];
    const int nk = (K + BK - 1) / BK;

    auto loadA = [&](int k0) {
        int gr = rowBase + aRow;
        #pragma unroll
        for (int i = 0; i < 2; i++) {
            int gk = k0 + aK + i * 4;
            float4 v = make_float4(0.f, 0.f, 0.f, 0.f);
            if (gr < M) {
                if (gk + 4 <= K) {
                    v = *reinterpret_cast<const float4*>(&A[(size_t)gr * K + gk]);
                } else if (gk < K) {
                    float t[4] = {0.f, 0.f, 0.f, 0.f};
                    #pragma unroll
                    for (int j = 0; j < 4; j++)
                        if (gk + j < K) t[j] = A[(size_t)gr * K + gk + j];
                    v = make_float4(t[0], t[1], t[2], t[3]);
                }
            }
            aReg[i] = v;
        }
    };
    auto loadB = [&](int k0) {
        int gk = k0 + bRow;
        #pragma unroll
        for (int i = 0; i < NV; i++) {
            int gc = colBase + bCol + i * 4;
            float4 v = make_float4(0.f, 0.f, 0.f, 0.f);
            if (gk < K && gc + 4 <= N)       // N%4==0: fully in or fully out
                v = *reinterpret_cast<const float4*>(&B[(size_t)gk * N + gc]);
            bReg[i] = v;
        }
    };
    auto storeTiles = [&](int buf) {
        #pragma unroll
        for (int i = 0; i < 2; i++) {
            As[buf][aK + i * 4 + 0][aRow] = aReg[i].x;
            As[buf][aK + i * 4 + 1][aRow] = aReg[i].y;
            As[buf][aK + i * 4 + 2][aRow] = aReg[i].z;
            As[buf][aK + i * 4 + 3][aRow] = aReg[i].w;
        }
        #pragma unroll
        for (int i = 0; i < NV; i++)
            *reinterpret_cast<float4*>(&Bs[buf][bRow][bCol + i * 4]) = bReg[i];
    };

    loadA(0); loadB(0);
    storeTiles(0);
    __syncthreads();

    int buf = 0;
    for (int t = 0; t < nk; t++) {
        if (t + 1 < nk) { loadA((t + 1) * BK); loadB((t + 1) * BK); }

        #pragma unroll
        for (int kk = 0; kk < BK; kk++) {
            float ra[8], rb[TN_];
            float4 a0 = *reinterpret_cast<const float4*>(&As[buf][kk][ty * 8]);
            float4 a1 = *reinterpret_cast<const float4*>(&As[buf][kk][ty * 8 + 4]);
            ra[0]=a0.x; ra[1]=a0.y; ra[2]=a0.z; ra[3]=a0.w;
            ra[4]=a1.x; ra[5]=a1.y; ra[6]=a1.z; ra[7]=a1.w;
            #pragma unroll
            for (int j = 0; j < TN_ / 4; j++) {
                float4 b = *reinterpret_cast<const float4*>(&Bs[buf][kk][tx * TN_ + j * 4]);
                rb[j*4+0]=b.x; rb[j*4+1]=b.y; rb[j*4+2]=b.z; rb[j*4+3]=b.w;
            }
            #pragma unroll
            for (int i = 0; i < 8; i++)
                #pragma unroll
                for (int j = 0; j < TN_; j++)
                    acc[i][j] += ra[i] * rb[j];
        }

        if (t + 1 < nk) {
            storeTiles(buf ^ 1);
            __syncthreads();
            buf ^= 1;
        }
    }

    #pragma unroll
    for (int i = 0; i < 8; i++) {
        int gr = rowBase + ty * 8 + i;
        if (gr >= M) continue;
        #pragma unroll
        for (int j = 0; j < TN_; j += 4) {
            int gc = colBase + tx * TN_ + j;
            if (gc + 4 <= N) {
                float4 v = make_float4(acc[i][j], acc[i][j+1], acc[i][j+2], acc[i][j+3]);
                *reinterpret_cast<float4*>(&C[(size_t)gr * N + gc]) = v;
            } else {
                #pragma unroll
                for (int q = 0; q < 4; q++)
                    if (gc + q < N) C[(size_t)gr * N + gc + q] = acc[i][j + q];
            }
        }
    }
}

// ---------------- fused gather-aggregate + bias (+relu), F=628 --------------
// out[i,f] = (relu?)( dinv[i]^2*H[i,f] + sum_e w_e*H[src_e,f] + bias[f] )
__global__ __launch_bounds__(256) void k_agg628(
    const float* __restrict__ H, float* __restrict__ out,
    const int* __restrict__ rowSt, const int* __restrict__ cnt,
    const int* __restrict__ eSrc, const float* __restrict__ eW,
    const float* __restrict__ dinv, const float* __restrict__ bias,
    int relu)
{
    const int node = blockIdx.x;
    const int tid  = threadIdx.x;
    const int f0 = tid, f1 = tid + 256, f2 = tid + 512;
    const bool has2 = (f2 < F1);

    const float dv = dinv[node];
    const float ws = dv * dv;
    const float* hn = H + (size_t)node * F1;
    float a0 = ws * hn[f0];
    float a1 = ws * hn[f1];
    float a2 = has2 ? ws * hn[f2] : 0.0f;

    const int beg = rowSt[node];
    const int end = beg + cnt[node];
    for (int e = beg; e < end; e++) {
        int s   = eSrc[e];
        float w = eW[e];
        const float* hs = H + (size_t)s * F1;
        a0 += w * hs[f0];
        a1 += w * hs[f1];
        if (has2) a2 += w * hs[f2];
    }

    float* o = out + (size_t)node * F1;
    float v0 = a0 + bias[f0];
    float v1 = a1 + bias[f1];
    if (relu) { v0 = fmaxf(v0, 0.f); v1 = fmaxf(v1, 0.f); }
    o[f0] = v0;
    o[f1] = v1;
    if (has2) {
        float v2 = a2 + bias[f2];
        if (relu) v2 = fmaxf(v2, 0.f);
        o[f2] = v2;
    }
}

// ---------------- fused gather-aggregate + bias, F=64 -----------------------
__global__ __launch_bounds__(64) void k_agg64(
    const float* __restrict__ H, float* __restrict__ out,
    const int* __restrict__ rowSt, const int* __restrict__ cnt,
    const int* __restrict__ eSrc, const float* __restrict__ eW,
    const float* __restrict__ dinv, const float* __restrict__ bias)
{
    const int node = blockIdx.x;
    const int f = threadIdx.x;

    const float dv = dinv[node];
    float acc = dv * dv * H[(size_t)node * F2 + f];

    const int beg = rowSt[node];
    const int end = beg + cnt[node];
    for (int e = beg; e < end; e++) {
        int s   = eSrc[e];
        float w = eW[e];
        acc += w * H[(size_t)s * F2 + f];
    }
    out[(size_t)node * F2 + f] = acc + bias[f];
}

// ---------------- decoder: logits[e] = dot(Z[src], Z[dst]) over 64 dims -----
__global__ void k_edge_dot(const float* __restrict__ Z, const int* __restrict__ src,
                           const int* __restrict__ dst, float* __restrict__ out, int e)
{
    int edge = blockIdx.x * (blockDim.x >> 5) + (threadIdx.x >> 5);
    int lane = threadIdx.x & 31;
    if (edge >= e) return;
    int s = src[edge], d = dst[edge];
    const float* zs = Z + (size_t)s * F2;
    const float* zd = Z + (size_t)d * F2;
    float acc = zs[lane] * zd[lane] + zs[lane + 32] * zd[lane + 32];
    #pragma unroll
    for (int o = 16; o > 0; o >>= 1)
        acc += __shfl_xor_sync(0xFFFFFFFFu, acc, o);
    if (lane == 0) out[edge] = acc;
}

// ---------------- launch ----------------------------------------------------
static inline int cdiv(long long a, long long b) { return (int)((a + b - 1) / b); }

extern "C" void kernel_launch(void* const* d_in, const int* in_sizes, int n_in,
                              void* d_out, int out_size)
{
    const float* x   = (const float*)d_in[0];
    const int*   ei  = (const int*)  d_in[1];
    const float* W1  = (const float*)d_in[2];
    const float* b1  = (const float*)d_in[3];
    const float* W2  = (const float*)d_in[4];
    const float* b2  = (const float*)d_in[5];
    float* logits    = (float*)d_out;

    int N = in_sizes[0] / F0;
    int E = in_sizes[1] / 2;
    const int* src = ei;
    const int* dst = ei + E;

    int *cnt, *rowSt, *cursor, *bsum, *eSrc;
    float *dinv, *eW, *H1, *A1, *H2, *Z;
    cudaGetSymbolAddress((void**)&cnt,    g_cnt);
    cudaGetSymbolAddress((void**)&rowSt,  g_rowSt);
    cudaGetSymbolAddress((void**)&cursor, g_cursor);
    cudaGetSymbolAddress((void**)&bsum,   g_bsum);
    cudaGetSymbolAddress((void**)&eSrc,   g_eSrc);
    cudaGetSymbolAddress((void**)&dinv,   g_dinv);
    cudaGetSymbolAddress((void**)&eW,     g_eW);
    cudaGetSymbolAddress((void**)&H1,     g_H1);
    cudaGetSymbolAddress((void**)&A1,     g_A1);
    cudaGetSymbolAddress((void**)&H2,     g_H2);
    cudaGetSymbolAddress((void**)&Z,      g_Z);

    const int nScanBlk = cdiv(N, SCAN_BLK);

    // ---- CSR build (deg, dinv, prefix, fill) ----
    k_zero_cnt<<<cdiv(N, 256), 256>>>(cnt, N);
    k_count   <<<cdiv(E, 256), 256>>>(cnt, dst, E);
    k_dinv    <<<cdiv(N, 256), 256>>>(dinv, cnt, N);
    k_scan1   <<<nScanBlk, SCAN_BLK>>>(cnt, rowSt, bsum, N);
    k_scan2   <<<1, 32>>>(bsum, nScanBlk);
    k_scan3   <<<nScanBlk, SCAN_BLK>>>(rowSt, bsum, cursor, N);
    k_fill    <<<cdiv(E, 256), 256>>>(src, dst, cursor, eSrc, eW, dinv, E);

    // ---- layer 1: H1 = x @ W1 ; A1 = aggregate + b1 ; relu ----
    {
        dim3 grid(cdiv(F1, 128), cdiv(N, BM));
        k_sgemm<128, 8><<<grid, 256>>>(x, W1, H1, N, F1, F0);
    }
    k_agg628<<<N, 256>>>(H1, A1, rowSt, cnt, eSrc, eW, dinv, b1, 1);

    // ---- layer 2: H2 = A1 @ W2 ; Z = aggregate + b2 ----
    {
        dim3 grid(cdiv(F2, 64), cdiv(N, BM));
        k_sgemm<64, 4><<<grid, 256>>>(A1, W2, H2, N, F2, F1);
    }
    k_agg64<<<N, 64>>>(H2, Z, rowSt, cnt, eSrc, eW, dinv, b2);

    // ---- decoder ----
    k_edge_dot<<<cdiv(E, 8), 256>>>(Z, src, dst, logits, E);
}

// round 13
// speedup vs baseline: 1.1731x; 1.1731x over previous
#include <cuda_runtime.h>
#include <math.h>

// Problem constants (fixed by the dataset)
#define NN 50000      // nodes
#define F0 600        // input features
#define F1 628        // hidden features
#define F2 64        // output features
#define EE 400000     // edges

// ---------------- scratch (device globals: no allocations allowed) ----------
__device__ int   g_cnt   [NN];        // in-degree (excl. self-loop)
__device__ int   g_rowSt [NN];        // exclusive prefix of cnt
__device__ int   g_cursor[NN];        // fill cursors
__device__ int   g_bsum  [64];        // scan block sums
__device__ float g_dinv  [NN];
__device__ int   g_eSrc  [EE];        // CSR: src node per slot
__device__ float g_eW    [EE];        // CSR: dinv[s]*dinv[d] per slot
__device__ float g_H1[(size_t)NN * F1];   // x @ W1
__device__ float g_A1[(size_t)NN * F1];   // aggregated + bias + relu
__device__ float g_H2[(size_t)NN * F2];   // A1 @ W2
__device__ float g_Z [(size_t)NN * F2];   // aggregated + bias

// ---------------- degree / normalization / CSR build ------------------------
__global__ void k_zero_cnt(int* cnt, int n) {
    int i = blockIdx.x * blockDim.x + threadIdx.x;
    if (i < n) cnt[i] = 0;
}
__global__ void k_count(int* cnt, const int* __restrict__ dst, int e) {
    int i = blockIdx.x * blockDim.x + threadIdx.x;
    if (i < e) atomicAdd(&cnt[dst[i]], 1);
}
__global__ void k_dinv(float* dinv, const int* __restrict__ cnt, int n) {
    int i = blockIdx.x * blockDim.x + threadIdx.x;
    if (i < n) dinv[i] = rsqrtf((float)(cnt[i] + 1));   // +1 self-loop
}

#define SCAN_BLK 1024
__global__ void k_scan1(const int* __restrict__ cnt, int* __restrict__ excl,
                        int* __restrict__ bsum, int n)
{
    __shared__ int sh[SCAN_BLK];
    int i = blockIdx.x * SCAN_BLK + threadIdx.x;
    int v = (i < n) ? cnt[i] : 0;
    sh[threadIdx.x] = v;
    __syncthreads();
    #pragma unroll
    for (int off = 1; off < SCAN_BLK; off <<= 1) {
        int t = (threadIdx.x >= off) ? sh[threadIdx.x - off] : 0;
        __syncthreads();
        sh[threadIdx.x] += t;
        __syncthreads();
    }
    if (i < n) excl[i] = sh[threadIdx.x] - v;            // exclusive within block
    if (threadIdx.x == SCAN_BLK - 1) bsum[blockIdx.x] = sh[threadIdx.x];
}
__global__ void k_scan2(int* bsum, int nb) {
    if (threadIdx.x == 0 && blockIdx.x == 0) {
        int s = 0;
        for (int i = 0; i < nb; i++) { int t = bsum[i]; bsum[i] = s; s += t; }
    }
}
__global__ void k_scan3(int* __restrict__ excl, const int* __restrict__ bsum,
                        int* __restrict__ cursor, int n)
{
    int i = blockIdx.x * SCAN_BLK + threadIdx.x;
    if (i < n) {
        int r = excl[i] + bsum[blockIdx.x];
        excl[i] = r;
        cursor[i] = r;
    }
}
__global__ void k_fill(const int* __restrict__ src, const int* __restrict__ dst,
                       int* cursor, int* __restrict__ eSrc, float* __restrict__ eW,
                       const float* __restrict__ dinv, int e)
{
    int i = blockIdx.x * blockDim.x + threadIdx.x;
    if (i < e) {
        int s = src[i], d = dst[i];
        int pos = atomicAdd(&cursor[d], 1);
        eSrc[pos] = s;
        eW[pos]   = dinv[s] * dinv[d];
    }
}

// ---------------- tiled SGEMM: C[M,N] = A[M,K] @ B[K,N] ---------------------
// 256 threads, BM=128, BK=16, templated BN/TN. Double-buffered smem,
// float4 global loads, packed fma.rn.f32x2 (FFMA2) inner loop.
#define BM 128
#define BK 16

template <int BN_, int TN_>
__global__ __launch_bounds__(256) void k_sgemm(
    const float* __restrict__ A, const float* __restrict__ B,
    float* __restrict__ C, int M, int N, int K)
{
    static_assert(BN_ / TN_ == 16, "16 col groups required");
    static_assert(TN_ % 2 == 0, "paired accumulators");
    constexpr int NV = BN_ / 64;            // float4s per thread for B tile
    constexpr int NP = TN_ / 2;             // packed pairs per row

    __shared__ __align__(16) float As[2][BK][BM];
    __shared__ __align__(16) float Bs[2][BK][BN_ + 4];
    // row stride of Bs = (BN_+4)*4 bytes: 528 (BN=128) / 272 (BN=64), both %16==0
    static_assert(((BN_ + 4) * 4) % 16 == 0, "Bs rows must stay 16B aligned");

    const int tid = threadIdx.x;
    const int tx  = tid & 15;               // col group (TN_ cols)
    const int ty  = tid >> 4;               // row group (8 rows)
    const int rowBase = blockIdx.y * BM;
    const int colBase = blockIdx.x * BN_;

    // A tile (128x16): 2 threads/row, 8 consecutive k each (2 float4)
    const int aRow = tid >> 1;
    const int aK   = (tid & 1) * 8;
    // B tile (16xBN_): 16 threads/row, 4*NV consecutive cols each
    const int bRow = tid >> 4;
    const int bCol = (tid & 15) * 4 * NV;

    // packed f32x2 accumulators: acc2[i][p] holds C cols (2p, 2p+1) for row i
    unsigned long long acc2[8][NP];
    #pragma unroll
    for (int i = 0; i < 8; i++)
        #pragma unroll
        for (int p = 0; p < NP; p++) acc2[i][p] = 0ULL;   // {0.0f, 0.0f}

    float4 aReg[2], bReg[NV];
    const int nk = (K + BK - 1) / BK;

    auto loadA = [&](int k0) {
        int gr = rowBase + aRow;
        #pragma unroll
        for (int i = 0; i < 2; i++) {
            int gk = k0 + aK + i * 4;
            float4 v = make_float4(0.f, 0.f, 0.f, 0.f);
            if (gr < M) {
                if (gk + 4 <= K) {
                    v = *reinterpret_cast<const float4*>(&A[(size_t)gr * K + gk]);
                } else if (gk < K) {
                    float t[4] = {0.f, 0.f, 0.f, 0.f};
                    #pragma unroll
                    for (int j = 0; j < 4; j++)
                        if (gk + j < K) t[j] = A[(size_t)gr * K + gk + j];
                    v = make_float4(t[0], t[1], t[2], t[3]);
                }
            }
            aReg[i] = v;
        }
    };
    auto loadB = [&](int k0) {
        int gk = k0 + bRow;
        #pragma unroll
        for (int i = 0; i < NV; i++) {
            int gc = colBase + bCol + i * 4;
            float4 v = make_float4(0.f, 0.f, 0.f, 0.f);
            if (gk < K && gc + 4 <= N)       // N%4==0: fully in or fully out
                v = *reinterpret_cast<const float4*>(&B[(size_t)gk * N + gc]);
            bReg[i] = v;
        }
    };
    auto storeTiles = [&](int buf) {
        #pragma unroll
        for (int i = 0; i < 2; i++) {
            As[buf][aK + i * 4 + 0][aRow] = aReg[i].x;
            As[buf][aK + i * 4 + 1][aRow] = aReg[i].y;
            As[buf][aK + i * 4 + 2][aRow] = aReg[i].z;
            As[buf][aK + i * 4 + 3][aRow] = aReg[i].w;
        }
        #pragma unroll
        for (int i = 0; i < NV; i++)
            *reinterpret_cast<float4*>(&Bs[buf][bRow][bCol + i * 4]) = bReg[i];
    };

    loadA(0); loadB(0);
    storeTiles(0);
    __syncthreads();

    int buf = 0;
    for (int t = 0; t < nk; t++) {
        if (t + 1 < nk) { loadA((t + 1) * BK); loadB((t + 1) * BK); }

        #pragma unroll
        for (int kk = 0; kk < BK; kk++) {
            // A fragment (8 rows)
            float ra[8];
            float4 a0 = *reinterpret_cast<const float4*>(&As[buf][kk][ty * 8]);
            float4 a1 = *reinterpret_cast<const float4*>(&As[buf][kk][ty * 8 + 4]);
            ra[0]=a0.x; ra[1]=a0.y; ra[2]=a0.z; ra[3]=a0.w;
            ra[4]=a1.x; ra[5]=a1.y; ra[6]=a1.z; ra[7]=a1.w;
            // B fragment as packed 64-bit pairs straight from smem
            unsigned long long bb[NP];
            #pragma unroll
            for (int q = 0; q < NP / 2; q++) {
                ulonglong2 b2 = *reinterpret_cast<const ulonglong2*>(
                    &Bs[buf][kk][tx * TN_ + q * 4]);
                bb[q * 2]     = b2.x;
                bb[q * 2 + 1] = b2.y;
            }
            #pragma unroll
            for (int i = 0; i < 8; i++) {
                unsigned long long aa;
                asm("mov.b64 %0, {%1, %1};" : "=l"(aa) : "f"(ra[i]));
                #pragma unroll
                for (int p = 0; p < NP; p++)
                    asm("fma.rn.f32x2 %0, %1, %2, %0;"
                        : "+l"(acc2[i][p]) : "l"(aa), "l"(bb[p]));
            }
        }

        if (t + 1 < nk) {
            storeTiles(buf ^ 1);
            __syncthreads();
            buf ^= 1;
        }
    }

    // epilogue: unpack pairs and store
    #pragma unroll
    for (int i = 0; i < 8; i++) {
        int gr = rowBase + ty * 8 + i;
        if (gr >= M) continue;
        float acc[TN_];
        #pragma unroll
        for (int p = 0; p < NP; p++) {
            unsigned lo, hi;
            asm("mov.b64 {%0, %1}, %2;" : "=r"(lo), "=r"(hi) : "l"(acc2[i][p]));
            acc[p * 2]     = __uint_as_float(lo);
            acc[p * 2 + 1] = __uint_as_float(hi);
        }
        #pragma unroll
        for (int j = 0; j < TN_; j += 4) {
            int gc = colBase + tx * TN_ + j;
            if (gc + 4 <= N) {
                float4 v = make_float4(acc[j], acc[j+1], acc[j+2], acc[j+3]);
                *reinterpret_cast<float4*>(&C[(size_t)gr * N + gc]) = v;
            } else {
                #pragma unroll
                for (int q = 0; q < 4; q++)
                    if (gc + q < N) C[(size_t)gr * N + gc + q] = acc[j + q];
            }
        }
    }
}

// ---------------- fused gather-aggregate + bias (+relu), F=628, float4 ------
// out[i, 4v..4v+3] = relu?( dinv[i]^2*H[i] + sum_e w_e*H[src_e] + bias )
// 160 threads/node; threads 157..159 idle (no syncs). F1/4 = 157 float4s.
__global__ __launch_bounds__(160) void k_agg628(
    const float* __restrict__ H, float* __restrict__ out,
    const int* __restrict__ rowSt, const int* __restrict__ cnt,
    const int* __restrict__ eSrc, const float* __restrict__ eW,
    const float* __restrict__ dinv, const float* __restrict__ bias,
    int relu)
{
    const int node = blockIdx.x;
    const int v = threadIdx.x;              // float4 column index
    if (v >= F1 / 4) return;                // 157 active threads

    const float dv = dinv[node];
    const float ws = dv * dv;
    const float4* hn = reinterpret_cast<const float4*>(H + (size_t)node * F1);
    float4 h = hn[v];
    float4 a = make_float4(ws * h.x, ws * h.y, ws * h.z, ws * h.w);

    const int beg = rowSt[node];
    const int end = beg + cnt[node];
    for (int e = beg; e < end; e++) {
        int s   = eSrc[e];
        float w = eW[e];
        float4 hs = reinterpret_cast<const float4*>(H + (size_t)s * F1)[v];
        a.x += w * hs.x; a.y += w * hs.y; a.z += w * hs.z; a.w += w * hs.w;
    }

    float4 b = reinterpret_cast<const float4*>(bias)[v];
    a.x += b.x; a.y += b.y; a.z += b.z; a.w += b.w;
    if (relu) {
        a.x = fmaxf(a.x, 0.f); a.y = fmaxf(a.y, 0.f);
        a.z = fmaxf(a.z, 0.f); a.w = fmaxf(a.w, 0.f);
    }
    reinterpret_cast<float4*>(out + (size_t)node * F1)[v] = a;
}

// ---------------- fused gather-aggregate + bias, F=64, float4 ---------------
// 16 threads per node (16 float4 columns), 8 nodes per 128-thread block.
__global__ __launch_bounds__(128) void k_agg64(
    const float* __restrict__ H, float* __restrict__ out,
    const int* __restrict__ rowSt, const int* __restrict__ cnt,
    const int* __restrict__ eSrc, const float* __restrict__ eW,
    const float* __restrict__ dinv, const float* __restrict__ bias, int n)
{
    const int node = blockIdx.x * 8 + (threadIdx.x >> 4);
    const int v    = threadIdx.x & 15;      // float4 column index (F2/4 = 16)
    if (node >= n) return;

    const float dv = dinv[node];
    const float ws = dv * dv;
    float4 h = reinterpret_cast<const float4*>(H + (size_t)node * F2)[v];
    float4 a = make_float4(ws * h.x, ws * h.y, ws * h.z, ws * h.w);

    const int beg = rowSt[node];
    const int end = beg + cnt[node];
    for (int e = beg; e < end; e++) {
        int s   = eSrc[e];
        float w = eW[e];
        float4 hs = reinterpret_cast<const float4*>(H + (size_t)s * F2)[v];
        a.x += w * hs.x; a.y += w * hs.y; a.z += w * hs.z; a.w += w * hs.w;
    }

    float4 b = reinterpret_cast<const float4*>(bias)[v];
    a.x += b.x; a.y += b.y; a.z += b.z; a.w += b.w;
    reinterpret_cast<float4*>(out + (size_t)node * F2)[v] = a;
}

// ---------------- decoder: logits[e] = dot(Z[src], Z[dst]) over 64 dims -----
__global__ void k_edge_dot(const float* __restrict__ Z, const int* __restrict__ src,
                           const int* __restrict__ dst, float* __restrict__ out, int e)
{
    int edge = blockIdx.x * (blockDim.x >> 5) + (threadIdx.x >> 5);
    int lane = threadIdx.x & 31;
    if (edge >= e) return;
    int s = src[edge], d = dst[edge];
    const float* zs = Z + (size_t)s * F2;
    const float* zd = Z + (size_t)d * F2;
    float acc = zs[lane] * zd[lane] + zs[lane + 32] * zd[lane + 32];
    #pragma unroll
    for (int o = 16; o > 0; o >>= 1)
        acc += __shfl_xor_sync(0xFFFFFFFFu, acc, o);
    if (lane == 0) out[edge] = acc;
}

// ---------------- launch ----------------------------------------------------
static inline int cdiv(long long a, long long b) { return (int)((a + b - 1) / b); }

extern "C" void kernel_launch(void* const* d_in, const int* in_sizes, int n_in,
                              void* d_out, int out_size)
{
    const float* x   = (const float*)d_in[0];
    const int*   ei  = (const int*)  d_in[1];
    const float* W1  = (const float*)d_in[2];
    const float* b1  = (const float*)d_in[3];
    const float* W2  = (const float*)d_in[4];
    const float* b2  = (const float*)d_in[5];
    float* logits    = (float*)d_out;

    int N = in_sizes[0] / F0;
    int E = in_sizes[1] / 2;
    const int* src = ei;
    const int* dst = ei + E;

    int *cnt, *rowSt, *cursor, *bsum, *eSrc;
    float *dinv, *eW, *H1, *A1, *H2, *Z;
    cudaGetSymbolAddress((void**)&cnt,    g_cnt);
    cudaGetSymbolAddress((void**)&rowSt,  g_rowSt);
    cudaGetSymbolAddress((void**)&cursor, g_cursor);
    cudaGetSymbolAddress((void**)&bsum,   g_bsum);
    cudaGetSymbolAddress((void**)&eSrc,   g_eSrc);
    cudaGetSymbolAddress((void**)&dinv,   g_dinv);
    cudaGetSymbolAddress((void**)&eW,     g_eW);
    cudaGetSymbolAddress((void**)&H1,     g_H1);
    cudaGetSymbolAddress((void**)&A1,     g_A1);
    cudaGetSymbolAddress((void**)&H2,     g_H2);
    cudaGetSymbolAddress((void**)&Z,      g_Z);

    const int nScanBlk = cdiv(N, SCAN_BLK);

    // ---- CSR build (deg, dinv, prefix, fill) ----
    k_zero_cnt<<<cdiv(N, 256), 256>>>(cnt, N);
    k_count   <<<cdiv(E, 256), 256>>>(cnt, dst, E);
    k_dinv    <<<cdiv(N, 256), 256>>>(dinv, cnt, N);
    k_scan1   <<<nScanBlk, SCAN_BLK>>>(cnt, rowSt, bsum, N);
    k_scan2   <<<1, 32>>>(bsum, nScanBlk);
    k_scan3   <<<nScanBlk, SCAN_BLK>>>(rowSt, bsum, cursor, N);
    k_fill    <<<cdiv(E, 256), 256>>>(src, dst, cursor, eSrc, eW, dinv, E);

    // ---- layer 1: H1 = x @ W1 ; A1 = aggregate + b1 ; relu ----
    {
        dim3 grid(cdiv(F1, 128), cdiv(N, BM));
        k_sgemm<128, 8><<<grid, 256>>>(x, W1, H1, N, F1, F0);
    }
    k_agg628<<<N, 160>>>(H1, A1, rowSt, cnt, eSrc, eW, dinv, b1, 1);

    // ---- layer 2: H2 = A1 @ W2 ; Z = aggregate + b2 ----
    {
        dim3 grid(cdiv(F2, 64), cdiv(N, BM));
        k_sgemm<64, 4><<<grid, 256>>>(A1, W2, H2, N, F2, F1);
    }
    k_agg64<<<cdiv(N, 8), 128>>>(H2, Z, rowSt, cnt, eSrc, eW, dinv, b2, N);

    // ---- decoder ----
    k_edge_dot<<<cdiv(E, 8), 256>>>(Z, src, dst, logits, E);
}